// round 10
// baseline (speedup 1.0000x reference)
#include <cuda_runtime.h>
#include <cstdint>

#define BB 4
#define LL 8192
#define DD 512
#define NCH 512        // chunks along L
#define CLH 16         // chunk length = LL/NCH
#define D4 (DD/4)      // 128 float4 channels
#define LOOK 8         // lookback batch size

// Per (b, chunk, d): aggregate and inclusive-prefix complex states (SoA).
__device__ float g_ar[BB * NCH * DD];
__device__ float g_ai[BB * NCH * DD];
__device__ float g_pr[BB * NCH * DD];
__device__ float g_pi[BB * NCH * DD];
__device__ int   g_flag[BB * NCH];    // 0 = empty, 1 = aggregate ready, 2 = prefix ready

__global__ void zero_flags() {
    int i = blockIdx.x * blockDim.x + threadIdx.x;
    if (i < BB * NCH) g_flag[i] = 0;
}

__device__ __forceinline__ void cp_async16(uint32_t smem_addr, const void* gptr) {
    asm volatile("cp.async.cg.shared.global [%0], [%1], 16;\n"
                 :: "r"(smem_addr), "l"(gptr));
}
__device__ __forceinline__ void cp_commit() {
    asm volatile("cp.async.commit_group;\n");
}
template <int N>
__device__ __forceinline__ void cp_wait() {
    asm volatile("cp.async.wait_group %0;\n" :: "n"(N));
}

// ---------------------------------------------------------------------------
// Fused single-pass LRU scan with decoupled lookback.
// grid = (NCH, BB), block = 128; each thread owns 4 channels.
// x is read from DRAM exactly once (into SMEM), y written once.
// ---------------------------------------------------------------------------
__global__ void __launch_bounds__(128)
lru_fused(const float* __restrict__ x,
          const float* __restrict__ nu,
          const float* __restrict__ theta,
          const float* __restrict__ gre,
          const float* __restrict__ gim,
          float* __restrict__ out) {
    __shared__ float4 xs[CLH][D4];   // 32 KB: the whole chunk

    const int tid = threadIdx.x;     // 0..127
    const int c   = blockIdx.x;
    const int b   = blockIdx.y;

    // ---- kick off the chunk load first ----
    const float4* xp = (const float4*)(x + ((size_t)(b * LL + c * CLH)) * DD) + tid;
#pragma unroll
    for (int k = 0; k < CLH; k++) {
        uint32_t sa = (uint32_t)__cvta_generic_to_shared(&xs[k][tid]);
        cp_async16(sa, xp + (size_t)k * D4);
    }
    cp_commit();

    // ---- per-channel parameters while the loads fly ----
    const float4 nu4 = ((const float4*)nu)[tid];
    const float4 th4 = ((const float4*)theta)[tid];
    const float4 gr4 = ((const float4*)gre)[tid];
    const float4 gi4 = ((const float4*)gim)[tid];
    const float* grj = (const float*)&gr4;
    const float* gij = (const float*)&gi4;

    float lr[4], li[4], Lr[4], Li[4];   // lambda, lambda^CL
    {
        const float* nup = (const float*)&nu4;
        const float* thp = (const float*)&th4;
#pragma unroll
        for (int j = 0; j < 4; j++) {
            const float a = expf(nup[j]);
            const float mag = expf(-a);
            float s, co;
            sincosf(thp[j], &s, &co);
            lr[j] = mag * co;
            li[j] = mag * s;
            const float Lmag = expf(-(float)CLH * a);
            float S, C;
            sincosf((float)CLH * thp[j], &S, &C);
            Lr[j] = Lmag * C;
            Li[j] = Lmag * S;
        }
    }

    cp_wait<0>();
    __syncthreads();

    // ---- local scan from zero state (aggregate) ----
    float hr[4] = {0.f, 0.f, 0.f, 0.f};
    float hi[4] = {0.f, 0.f, 0.f, 0.f};
#pragma unroll
    for (int i = 0; i < CLH; i++) {
        const float4 xv = xs[i][tid];
        const float* xj = (const float*)&xv;
#pragma unroll
        for (int j = 0; j < 4; j++) {
            const float nhr = fmaf(lr[j], hr[j], fmaf(-li[j], hi[j], xj[j]));
            const float nhi = fmaf(li[j], hr[j], lr[j] * hi[j]);
            hr[j] = nhr;
            hi[j] = nhi;
        }
    }

    const int base_c = (b * NCH + c) * DD + 4 * tid;
    *(float4*)(g_ar + base_c) = make_float4(hr[0], hr[1], hr[2], hr[3]);
    *(float4*)(g_ai + base_c) = make_float4(hi[0], hi[1], hi[2], hi[3]);
    __syncthreads();
    if (tid == 0) {
        __threadfence();
        *(volatile int*)&g_flag[b * NCH + c] = 1;   // aggregate ready
    }

    // ---- decoupled lookback: incoming state for this chunk ----
    float inr[4] = {0.f, 0.f, 0.f, 0.f};
    float ini[4] = {0.f, 0.f, 0.f, 0.f};
    if (c > 0) {
        float pwr[4] = {1.f, 1.f, 1.f, 1.f};
        float pwi[4] = {0.f, 0.f, 0.f, 0.f};
        int j = c - 1;
        bool done = false;
        while (!done) {
            const int nb = (j + 1 < LOOK) ? (j + 1) : LOOK;
            int f[LOOK];
#pragma unroll
            for (int k = 0; k < LOOK; k++)
                f[k] = (k < nb) ? *(volatile int*)&g_flag[b * NCH + j - k] : 0;

            int m = 0, stopP = -1;
            for (int k = 0; k < nb; k++) {
                if (f[k] == 0) break;
                m = k + 1;
                if (f[k] == 2) { stopP = k; break; }
            }
            if (m == 0) continue;        // predecessors not ready yet — retry
            __threadfence();             // order flag reads before data reads

            // Preload aggregates for the ready run (independent loads batch).
            float4 vr[LOOK], vi[LOOK];
#pragma unroll
            for (int k = 0; k < LOOK; k++) {
                if (k < m) {
                    const int idx2 = (b * NCH + (j - k)) * DD + 4 * tid;
                    vr[k] = *(const float4*)(g_ar + idx2);
                    vi[k] = *(const float4*)(g_ai + idx2);
                }
            }
            // If the run ends at a published prefix, reload that one from prefix arrays.
            if (stopP >= 0) {
                const int idx2 = (b * NCH + (j - stopP)) * DD + 4 * tid;
                vr[stopP] = *(const float4*)(g_pr + idx2);
                vi[stopP] = *(const float4*)(g_pi + idx2);
            }

            for (int k = 0; k < m; k++) {
                const float* vrj = (const float*)&vr[k];
                const float* vij = (const float*)&vi[k];
#pragma unroll
                for (int q = 0; q < 4; q++) {
                    inr[q] = fmaf(pwr[q], vrj[q], fmaf(-pwi[q], vij[q], inr[q]));
                    ini[q] = fmaf(pwr[q], vij[q], fmaf(pwi[q], vrj[q], ini[q]));
                }
                if (k == stopP) { done = true; break; }
#pragma unroll
                for (int q = 0; q < 4; q++) {
                    const float npr = pwr[q] * Lr[q] - pwi[q] * Li[q];
                    const float npi = pwr[q] * Li[q] + pwi[q] * Lr[q];
                    pwr[q] = npr;
                    pwi[q] = npi;
                }
            }
            if (!done) {
                j -= m;
                if (j < 0) done = true;
            }
        }
    }

    // ---- publish inclusive prefix: P_c = Lambda^CL * incoming + aggregate ----
    {
        float pr[4], pi[4];
#pragma unroll
        for (int q = 0; q < 4; q++) {
            pr[q] = fmaf(Lr[q], inr[q], fmaf(-Li[q], ini[q], hr[q]));
            pi[q] = fmaf(Li[q], inr[q], fmaf(Lr[q], ini[q], hi[q]));
        }
        *(float4*)(g_pr + base_c) = make_float4(pr[0], pr[1], pr[2], pr[3]);
        *(float4*)(g_pi + base_c) = make_float4(pi[0], pi[1], pi[2], pi[3]);
    }
    __syncthreads();
    if (tid == 0) {
        __threadfence();
        *(volatile int*)&g_flag[b * NCH + c] = 2;   // prefix ready
    }

    // ---- final scan seeded with incoming state; emit outputs ----
    float4* yp = (float4*)(out + ((size_t)(b * LL + c * CLH)) * DD) + tid;
    float cr[4], ci[4];
#pragma unroll
    for (int q = 0; q < 4; q++) { cr[q] = inr[q]; ci[q] = ini[q]; }

#pragma unroll
    for (int i = 0; i < CLH; i++) {
        const float4 xv = xs[i][tid];
        const float* xj = (const float*)&xv;
        float4 yv;
        float* yj = (float*)&yv;
#pragma unroll
        for (int j = 0; j < 4; j++) {
            const float nhr = fmaf(lr[j], cr[j], fmaf(-li[j], ci[j], xj[j]));
            const float nhi = fmaf(li[j], cr[j], lr[j] * ci[j]);
            cr[j] = nhr;
            ci[j] = nhi;
            yj[j] = fmaf(grj[j], nhr, -gij[j] * nhi);
        }
        yp[(size_t)i * D4] = yv;
    }
}

// ---------------------------------------------------------------------------
extern "C" void kernel_launch(void* const* d_in, const int* in_sizes, int n_in,
                              void* d_out, int out_size) {
    const float* x     = (const float*)d_in[0];
    const float* nu    = (const float*)d_in[1];
    const float* theta = (const float*)d_in[2];
    const float* gre   = (const float*)d_in[3];
    const float* gim   = (const float*)d_in[4];
    float* out = (float*)d_out;

    zero_flags<<<(BB * NCH + 255) / 256, 256>>>();
    dim3 grid(NCH, BB);
    lru_fused<<<grid, D4>>>(x, nu, theta, gre, gim, out);
}

// round 11
// speedup vs baseline: 3.5757x; 3.5757x over previous
#include <cuda_runtime.h>
#include <cstdint>

#define BB 4
#define LL 8192
#define DD 512
#define NCH 64        // chunks along L  (all 256 blocks co-resident => depth-1 sync)
#define CLH 128       // chunk length = LL/NCH
#define D4 (DD/4)     // 128 float4 channels
#define LB 8          // lookback load batch

// Per (b, chunk, d): chunk aggregate (local scan from zero), SoA complex.
__device__ float g_ar[BB * NCH * DD];
__device__ float g_ai[BB * NCH * DD];
__device__ int   g_flag[BB * NCH];    // 0 = empty, 1 = aggregate published

__global__ void zero_flags() {
    int i = blockIdx.x * blockDim.x + threadIdx.x;
    if (i < BB * NCH) g_flag[i] = 0;
}

// ---------------------------------------------------------------------------
// Fused single-kernel LRU scan, depth-1 cross-chunk combine.
// grid = (NCH, BB) = 256 blocks, block = 128 threads, 4 channels/thread.
// Phase 1: local scan -> publish aggregate (all blocks run concurrently).
// Combine: sum ALL predecessor aggregates (batched L2 loads, no chain).
// Phase 2: re-scan x (L2-resident from phase 1), emit y.
// ---------------------------------------------------------------------------
__global__ void __launch_bounds__(128)
lru_fused(const float* __restrict__ x,
          const float* __restrict__ nu,
          const float* __restrict__ theta,
          const float* __restrict__ gre,
          const float* __restrict__ gim,
          float* __restrict__ out) {
    const int tid = threadIdx.x;     // 0..127
    const int c   = blockIdx.x;
    const int b   = blockIdx.y;

    // ---- per-channel parameters ----
    const float4 nu4 = ((const float4*)nu)[tid];
    const float4 th4 = ((const float4*)theta)[tid];
    const float4 gr4 = ((const float4*)gre)[tid];
    const float4 gi4 = ((const float4*)gim)[tid];
    const float* grj = (const float*)&gr4;
    const float* gij = (const float*)&gi4;

    float lr[4], li[4], Lr[4], Li[4];   // lambda, Lambda = lambda^CLH
    {
        const float* nup = (const float*)&nu4;
        const float* thp = (const float*)&th4;
#pragma unroll
        for (int j = 0; j < 4; j++) {
            const float a = expf(nup[j]);
            const float mag = expf(-a);
            float s, co;
            sincosf(thp[j], &s, &co);
            lr[j] = mag * co;
            li[j] = mag * s;
            const float Lmag = expf(-(float)CLH * a);
            float S, C;
            sincosf((float)CLH * thp[j], &S, &C);
            Lr[j] = Lmag * C;
            Li[j] = Lmag * S;
        }
    }

    const size_t base = ((size_t)(b * LL + c * CLH)) * DD;
    const float4* xp = (const float4*)(x + base) + tid;

    // ---- Phase 1: local scan from zero state ----
    float hr[4] = {0.f, 0.f, 0.f, 0.f};
    float hi[4] = {0.f, 0.f, 0.f, 0.f};
#pragma unroll 8
    for (int i = 0; i < CLH; i++) {
        const float4 xv = xp[(size_t)i * D4];
        const float* xj = (const float*)&xv;
#pragma unroll
        for (int j = 0; j < 4; j++) {
            const float nhr = fmaf(lr[j], hr[j], fmaf(-li[j], hi[j], xj[j]));
            const float nhi = fmaf(li[j], hr[j], lr[j] * hi[j]);
            hr[j] = nhr;
            hi[j] = nhi;
        }
    }

    const int base_c = (b * NCH + c) * DD + 4 * tid;
    *(float4*)(g_ar + base_c) = make_float4(hr[0], hr[1], hr[2], hr[3]);
    *(float4*)(g_ai + base_c) = make_float4(hi[0], hi[1], hi[2], hi[3]);
    __syncthreads();
    if (tid == 0) {
        __threadfence();
        *(volatile int*)&g_flag[b * NCH + c] = 1;   // aggregate published
    }

    // ---- Wait for ALL predecessors (depth-1: blocks are co-resident) ----
    if (tid < c) {
        while (*(volatile int*)&g_flag[b * NCH + tid] == 0) { }
    }
    __syncthreads();
    __threadfence();   // order flag observation before aggregate loads

    // ---- Combine: incoming = sum_{j<c} Lambda^(c-1-j) * A_j  (batched) ----
    float inr[4] = {0.f, 0.f, 0.f, 0.f};
    float ini[4] = {0.f, 0.f, 0.f, 0.f};
    {
        float pwr[4] = {1.f, 1.f, 1.f, 1.f};
        float pwi[4] = {0.f, 0.f, 0.f, 0.f};
        for (int j0 = c - 1; j0 >= 0; j0 -= LB) {
            const int m = (j0 + 1 < LB) ? (j0 + 1) : LB;
            float4 vr[LB], vi[LB];
#pragma unroll
            for (int k = 0; k < LB; k++) {
                if (k < m) {
                    const int idx2 = (b * NCH + (j0 - k)) * DD + 4 * tid;
                    vr[k] = *(const float4*)(g_ar + idx2);
                    vi[k] = *(const float4*)(g_ai + idx2);
                }
            }
#pragma unroll
            for (int k = 0; k < LB; k++) {
                if (k < m) {
                    const float* vrj = (const float*)&vr[k];
                    const float* vij = (const float*)&vi[k];
#pragma unroll
                    for (int q = 0; q < 4; q++) {
                        inr[q] = fmaf(pwr[q], vrj[q], fmaf(-pwi[q], vij[q], inr[q]));
                        ini[q] = fmaf(pwr[q], vij[q], fmaf(pwi[q], vrj[q], ini[q]));
                        const float npr = pwr[q] * Lr[q] - pwi[q] * Li[q];
                        const float npi = pwr[q] * Li[q] + pwi[q] * Lr[q];
                        pwr[q] = npr;
                        pwi[q] = npi;
                    }
                }
            }
        }
    }

    // ---- Phase 2: re-scan (x now L2-resident), emit outputs ----
    float4* yp = (float4*)(out + base) + tid;
    float cr[4], ci[4];
#pragma unroll
    for (int q = 0; q < 4; q++) { cr[q] = inr[q]; ci[q] = ini[q]; }

#pragma unroll 8
    for (int i = 0; i < CLH; i++) {
        const float4 xv = xp[(size_t)i * D4];
        const float* xj = (const float*)&xv;
        float4 yv;
        float* yj = (float*)&yv;
#pragma unroll
        for (int j = 0; j < 4; j++) {
            const float nhr = fmaf(lr[j], cr[j], fmaf(-li[j], ci[j], xj[j]));
            const float nhi = fmaf(li[j], cr[j], lr[j] * ci[j]);
            cr[j] = nhr;
            ci[j] = nhi;
            yj[j] = fmaf(grj[j], nhr, -gij[j] * nhi);
        }
        yp[(size_t)i * D4] = yv;
    }
}

// ---------------------------------------------------------------------------
extern "C" void kernel_launch(void* const* d_in, const int* in_sizes, int n_in,
                              void* d_out, int out_size) {
    const float* x     = (const float*)d_in[0];
    const float* nu    = (const float*)d_in[1];
    const float* theta = (const float*)d_in[2];
    const float* gre   = (const float*)d_in[3];
    const float* gim   = (const float*)d_in[4];
    float* out = (float*)d_out;

    zero_flags<<<1, 256>>>();
    dim3 grid(NCH, BB);
    lru_fused<<<grid, D4>>>(x, nu, theta, gre, gim, out);
}